// round 2
// baseline (speedup 1.0000x reference)
#include <cuda_runtime.h>

namespace {

constexpr int KNN = 32;   // K nearest neighbors
constexpr int IN2 = 64;   // 2K MLP input
constexpr int MID = 32;   // hidden width of fc2

__global__ __launch_bounds__(128) void meta_kernel(
    const int*   __restrict__ vals,
    const float* __restrict__ dist,
    const float* __restrict__ w1,   // [64,32]
    const float* __restrict__ b1,   // [32]
    const float* __restrict__ w2,   // [32,2]
    const float* __restrict__ b2,   // [2]
    const float* __restrict__ fw1,  // [2,4]
    const float* __restrict__ fb1,  // [4]
    const float* __restrict__ fw2,  // [4,1]
    const float* __restrict__ fb2,  // [1]
    float* __restrict__ out,        // [n,3]
    int n)
{
    __shared__ float s_w1[IN2 * MID];
    __shared__ float s_b1[MID];
    __shared__ float s_w2[MID * 2];

    const int tid = threadIdx.x;
    for (int i = tid; i < IN2 * MID; i += blockDim.x) s_w1[i] = w1[i];
    if (tid < MID)     s_b1[tid] = b1[tid];
    if (tid < MID * 2) s_w2[tid] = w2[tid];
    __syncthreads();

    const int e = blockIdx.x * blockDim.x + tid;
    if (e >= n) return;

    // ---- load this element's K labels + K distances (vectorized 16B) ----
    int v[KNN];
    {
        const int4* vp = reinterpret_cast<const int4*>(vals + (size_t)e * KNN);
        #pragma unroll
        for (int i = 0; i < KNN / 4; i++) {
            int4 t = vp[i];
            v[4*i+0] = t.x; v[4*i+1] = t.y; v[4*i+2] = t.z; v[4*i+3] = t.w;
        }
    }
    float x[IN2];
    {
        const float4* dp = reinterpret_cast<const float4*>(dist + (size_t)e * KNN);
        #pragma unroll
        for (int i = 0; i < KNN / 4; i++) {
            float4 t = dp[i];
            x[4*i+0] = t.x; x[4*i+1] = t.y; x[4*i+2] = t.z; x[4*i+3] = t.w;
        }
    }

    // ---- label_count_segment: x[32+k] = #distinct nonzero labels in v[0..k] ----
    int cnt = 0;
    #pragma unroll
    for (int k = 0; k < KNN; k++) {
        bool skip = (v[k] == 0);
        #pragma unroll
        for (int j = 0; j < k; j++) skip = skip || (v[j] == v[k]);
        cnt += skip ? 0 : 1;
        x[KNN + k] = (float)cnt;
    }

    // ---- fc2 layer 1: h = tanh(x @ W1 + b1), W1 broadcast from SMEM ----
    float h[MID];
    #pragma unroll
    for (int j = 0; j < MID / 4; j++) {
        float4 bb = reinterpret_cast<const float4*>(s_b1)[j];
        h[4*j+0] = bb.x; h[4*j+1] = bb.y; h[4*j+2] = bb.z; h[4*j+3] = bb.w;
    }
    #pragma unroll
    for (int i = 0; i < IN2; i++) {
        const float xi = x[i];
        const float4* wr = reinterpret_cast<const float4*>(s_w1 + i * MID);
        #pragma unroll
        for (int j = 0; j < MID / 4; j++) {
            float4 w = wr[j];
            h[4*j+0] = fmaf(xi, w.x, h[4*j+0]);
            h[4*j+1] = fmaf(xi, w.y, h[4*j+1]);
            h[4*j+2] = fmaf(xi, w.z, h[4*j+2]);
            h[4*j+3] = fmaf(xi, w.w, h[4*j+3]);
        }
    }

    // ---- fc2 layer 2: 2 outputs ----
    float o0 = b2[0], o1 = b2[1];
    #pragma unroll
    for (int j = 0; j < MID; j++) {
        const float hj = tanhf(h[j]);
        o0 = fmaf(hj, s_w2[2*j+0], o0);
        o1 = fmaf(hj, s_w2[2*j+1], o1);
    }

    // ---- fc1: Linear(2,4) -> tanh -> Linear(4,1) (uniform LDG, L1-resident) ----
    float o2 = fb2[0];
    #pragma unroll
    for (int m = 0; m < 4; m++) {
        const float t = tanhf(fb1[m] + fmaf(o0, fw1[m], o1 * fw1[4 + m]));
        o2 = fmaf(t, fw2[m], o2);
    }

    out[3*e+0] = o0;
    out[3*e+1] = o1;
    out[3*e+2] = o2;
}

} // anonymous namespace

extern "C" void kernel_launch(void* const* d_in, const int* in_sizes, int n_in,
                              void* d_out, int out_size) {
    const int*   vals = (const int*)  d_in[0];
    const float* dist = (const float*)d_in[1];
    const float* w1   = (const float*)d_in[2];
    const float* b1   = (const float*)d_in[3];
    const float* w2   = (const float*)d_in[4];
    const float* b2   = (const float*)d_in[5];
    const float* fw1  = (const float*)d_in[6];
    const float* fb1  = (const float*)d_in[7];
    const float* fw2  = (const float*)d_in[8];
    const float* fb2  = (const float*)d_in[9];
    float* out = (float*)d_out;

    const int n = in_sizes[0] / KNN;  // B*S elements
    const int threads = 128;
    const int blocks = (n + threads - 1) / threads;
    meta_kernel<<<blocks, threads>>>(vals, dist, w1, b1, w2, b2,
                                     fw1, fb1, fw2, fb2, out, n);
}

// round 4
// speedup vs baseline: 1.1429x; 1.1429x over previous
#include <cuda_runtime.h>

namespace {

constexpr int KNN  = 32;   // K nearest neighbors
constexpr int IN2  = 64;   // 2K MLP input
constexpr int MID  = 32;   // hidden width of fc2
constexpr int HALF = 16;   // hidden units per thread (2 threads per element)

__device__ __forceinline__ float fast_tanh(float x) {
    float y;
    asm("tanh.approx.f32 %0, %1;" : "=f"(y) : "f"(x));
    return y;
}

__global__ __launch_bounds__(128) void meta_kernel(
    const int*   __restrict__ vals,
    const float* __restrict__ dist,
    const float* __restrict__ w1,   // [64,32]
    const float* __restrict__ b1,   // [32]
    const float* __restrict__ w2,   // [32,2]
    const float* __restrict__ b2,   // [2]
    const float* __restrict__ fw1,  // [2,4]
    const float* __restrict__ fb1,  // [4]
    const float* __restrict__ fw2,  // [4,1]
    const float* __restrict__ fb2,  // [1]
    float* __restrict__ out,        // [n,3]
    int n)
{
    __shared__ float s_w1[IN2 * MID];
    __shared__ float s_b1[MID];
    __shared__ float s_w2[MID * 2];

    {
        const int tid = threadIdx.x;
        for (int i = tid; i < IN2 * MID; i += blockDim.x) s_w1[i] = w1[i];
        if (tid < MID)     s_b1[tid] = b1[tid];
        if (tid < MID * 2) s_w2[tid] = w2[tid];
        __syncthreads();
    }

    const int gt   = blockIdx.x * blockDim.x + threadIdx.x;
    const int e    = gt >> 1;          // element index
    const int half = gt & 1;           // which 16 hidden units this thread owns
    if (e >= n) return;
    const int off  = half * HALF;

    // ---- init accumulators with bias slice ----
    float h[HALF];
    #pragma unroll
    for (int j = 0; j < HALF / 4; j++) {
        float4 bb = *reinterpret_cast<const float4*>(s_b1 + off + 4 * j);
        h[4*j+0] = bb.x; h[4*j+1] = bb.y; h[4*j+2] = bb.z; h[4*j+3] = bb.w;
    }

    // ---- phase A: distances -> FMA directly into h (no x[] array) ----
    {
        const float4* dp = reinterpret_cast<const float4*>(dist + (size_t)e * KNN);
        #pragma unroll
        for (int c = 0; c < KNN / 4; c++) {
            float4 d4 = dp[c];
            float xs[4] = {d4.x, d4.y, d4.z, d4.w};
            #pragma unroll
            for (int r = 0; r < 4; r++) {
                const float xi = xs[r];
                const float4* wr =
                    reinterpret_cast<const float4*>(s_w1 + (c * 4 + r) * MID + off);
                #pragma unroll
                for (int j = 0; j < HALF / 4; j++) {
                    float4 w = wr[j];
                    h[4*j+0] = fmaf(xi, w.x, h[4*j+0]);
                    h[4*j+1] = fmaf(xi, w.y, h[4*j+1]);
                    h[4*j+2] = fmaf(xi, w.z, h[4*j+2]);
                    h[4*j+3] = fmaf(xi, w.w, h[4*j+3]);
                }
            }
        }
    }

    // ---- phase B: label counts, FMA each count into h as produced ----
    {
        int v[KNN];
        const int4* vp = reinterpret_cast<const int4*>(vals + (size_t)e * KNN);
        #pragma unroll
        for (int c = 0; c < KNN / 4; c++) {
            int4 t = vp[c];
            v[4*c+0] = t.x; v[4*c+1] = t.y; v[4*c+2] = t.z; v[4*c+3] = t.w;
        }

        int cnt = 0;
        #pragma unroll
        for (int k = 0; k < KNN; k++) {
            bool dup = (v[k] == 0);
            #pragma unroll
            for (int j = 0; j < k; j++) dup = dup || (v[j] == v[k]);
            cnt += dup ? 0 : 1;
            const float cf = (float)cnt;
            const float4* wr =
                reinterpret_cast<const float4*>(s_w1 + (KNN + k) * MID + off);
            #pragma unroll
            for (int j = 0; j < HALF / 4; j++) {
                float4 w = wr[j];
                h[4*j+0] = fmaf(cf, w.x, h[4*j+0]);
                h[4*j+1] = fmaf(cf, w.y, h[4*j+1]);
                h[4*j+2] = fmaf(cf, w.z, h[4*j+2]);
                h[4*j+3] = fmaf(cf, w.w, h[4*j+3]);
            }
        }
    }

    // ---- fc2 layer 2: partial sums over this thread's 16 hidden units ----
    float p0 = 0.f, p1 = 0.f;
    #pragma unroll
    for (int j = 0; j < HALF; j++) {
        const float t = fast_tanh(h[j]);
        p0 = fmaf(t, s_w2[2 * (off + j) + 0], p0);
        p1 = fmaf(t, s_w2[2 * (off + j) + 1], p1);
    }
    p0 += __shfl_xor_sync(0xffffffffu, p0, 1);
    p1 += __shfl_xor_sync(0xffffffffu, p1, 1);

    // ---- fc1 + store (even thread of the pair only) ----
    if (half == 0) {
        const float o0 = p0 + b2[0];
        const float o1 = p1 + b2[1];
        float o2 = fb2[0];
        #pragma unroll
        for (int m = 0; m < 4; m++) {
            const float t = fast_tanh(fb1[m] + fmaf(o0, fw1[m], o1 * fw1[4 + m]));
            o2 = fmaf(t, fw2[m], o2);
        }
        out[3*e+0] = o0;
        out[3*e+1] = o1;
        out[3*e+2] = o2;
    }
}

} // anonymous namespace

extern "C" void kernel_launch(void* const* d_in, const int* in_sizes, int n_in,
                              void* d_out, int out_size) {
    const int*   vals = (const int*)  d_in[0];
    const float* dist = (const float*)d_in[1];
    const float* w1   = (const float*)d_in[2];
    const float* b1   = (const float*)d_in[3];
    const float* w2   = (const float*)d_in[4];
    const float* b2   = (const float*)d_in[5];
    const float* fw1  = (const float*)d_in[6];
    const float* fb1  = (const float*)d_in[7];
    const float* fw2  = (const float*)d_in[8];
    const float* fb2  = (const float*)d_in[9];
    float* out = (float*)d_out;

    const int n = in_sizes[0] / KNN;        // B*S elements
    const int total = 2 * n;                // 2 threads per element
    const int threads = 128;
    const int blocks = (total + threads - 1) / threads;
    meta_kernel<<<blocks, threads>>>(vals, dist, w1, b1, w2, b2,
                                     fw1, fb1, fw2, fb2, out, n);
}